// round 17
// baseline (speedup 1.0000x reference)
#include <cuda_runtime.h>
#include <cstdint>

// FuzzyNeuron via mma.sync tf32 (3xTF32 logw, 1x tf32 z), fused kernel.
// R17: spill-proof software pipeline. Quantitative model from R16: HMMA
// rt ~7 cyc (tensor pipe only 24% busy) but runtime is 4x the throughput
// floor -> mma.sync RESULT latency (hundreds of cyc on sm_103's fallback
// path) is exposed once per chunk. Fix: ping-pong chunks so chunk j+1's
// 7 LDS + 14 MMAs separate chunk j's last MMA from its epilogue consumer.
// R15 tried this and SPILLED (struct/helper args @128-reg cap -> DRAM 11%).
// Here: pure macros (textual inline), launch_bounds(128,3)=168-reg budget,
// 1 m-tile/warp, rolled jj-pair loop (L0 I$-safe).

typedef unsigned int u32;

#define LOG2E 1.4426950408889634f
#define BLOCK 128
#define GRID 444       // 3 CTAs/SM x 148 SMs
#define NTILES 2048    // 131072 / 64 rows per CTA-tile

#define FL(j, ks, tig, g) (((j) * 4 + (ks)) * 40 + (tig) * 10 + (g))   // float4
#define FZ(j, ks, tig, g) (((j) * 2 + (ks)) * 48 + (tig) * 12 + (g))   // float2
#define FU(v) __float_as_uint(v)

__device__ __forceinline__ u32 tf32_bits(float v) {
    u32 r; asm("cvt.rna.tf32.f32 %0, %1;" : "=r"(r) : "f"(v)); return r;
}
__device__ __forceinline__ float exp2_fast(float v) {
    float r; asm("ex2.approx.ftz.f32 %0, %1;" : "=f"(r) : "f"(v)); return r;
}
// non-volatile: pure dataflow
__device__ __forceinline__ void mma8(float* c, const u32* a, u32 b0, u32 b1) {
    asm("mma.sync.aligned.m16n8k8.row.col.f32.tf32.tf32.f32 "
        "{%0,%1,%2,%3}, {%4,%5,%6,%7}, {%8,%9}, {%0,%1,%2,%3};"
        : "+f"(c[0]), "+f"(c[1]), "+f"(c[2]), "+f"(c[3])
        : "r"(a[0]), "r"(a[1]), "r"(a[2]), "r"(a[3]), "r"(b0), "r"(b1));
}

__device__ __forceinline__ float coefL(const float* mu, const float* sigma, int n, int k) {
    if (k < 16) {
        float m = mu[n * 16 + k], s = sigma[n * 16 + k];
        return 2.0f * __fdividef(0.5f, s * s) * m * LOG2E;      // multiplies x
    } else {
        float s = sigma[n * 16 + (k - 16)];
        return -__fdividef(0.5f, s * s) * LOG2E;                // multiplies x^2
    }
}

// Issue one chunk: 7 LDS + seed + 14 MMAs. Textual macro => no arg copies.
#define CHUNK_MMA(c1, c2, c3, cz, jj) do {                                   \
    float4 _B0 = sBl[FL((jj), 0, tig, g)];                                   \
    float4 _B1 = sBl[FL((jj), 1, tig, g)];                                   \
    float4 _B2 = sBl[FL((jj), 2, tig, g)];                                   \
    float4 _B3 = sBl[FL((jj), 3, tig, g)];                                   \
    float2 _Z0 = sBz[FZ((jj), 0, tig, g)];                                   \
    float2 _Z1 = sBz[FZ((jj), 1, tig, g)];                                   \
    float4 _q = *reinterpret_cast<const float4*>(&sFB[8 * (jj) + 2 * tig]);  \
    (c1)[0] = _q.x; (c1)[1] = _q.z; (c1)[2] = _q.x; (c1)[3] = _q.z;          \
    (c2)[0] = 0.f; (c2)[1] = 0.f; (c2)[2] = 0.f; (c2)[3] = 0.f;              \
    (c3)[0] = 0.f; (c3)[1] = 0.f; (c3)[2] = 0.f; (c3)[3] = 0.f;              \
    (cz)[0] = _q.y; (cz)[1] = _q.w; (cz)[2] = _q.y; (cz)[3] = _q.w;          \
    mma8((c1), ah[0], FU(_B0.x), FU(_B0.y));                                 \
    mma8((c2), al[0], FU(_B0.x), FU(_B0.y));                                 \
    mma8((c3), ah[0], FU(_B0.z), FU(_B0.w));                                 \
    mma8((c1), ah[1], FU(_B1.x), FU(_B1.y));                                 \
    mma8((c2), al[1], FU(_B1.x), FU(_B1.y));                                 \
    mma8((c3), ah[1], FU(_B1.z), FU(_B1.w));                                 \
    mma8((c1), ah[2], FU(_B2.x), FU(_B2.y));                                 \
    mma8((c2), al[2], FU(_B2.x), FU(_B2.y));                                 \
    mma8((c3), ah[2], FU(_B2.z), FU(_B2.w));                                 \
    mma8((c1), ah[3], FU(_B3.x), FU(_B3.y));                                 \
    mma8((c2), al[3], FU(_B3.x), FU(_B3.y));                                 \
    mma8((c3), ah[3], FU(_B3.z), FU(_B3.w));                                 \
    mma8((cz), ah[0], FU(_Z0.x), FU(_Z0.y));                                 \
    mma8((cz), ah[1], FU(_Z1.x), FU(_Z1.y));                                 \
} while (0)

#define CHUNK_EPI(c1, c2, c3, cz) do {                                       \
    float _w0 = exp2_fast((c1)[0] + (c2)[0] + (c3)[0]);                      \
    float _w1 = exp2_fast((c1)[1] + (c2)[1] + (c3)[1]);                      \
    float _w2 = exp2_fast((c1)[2] + (c2)[2] + (c3)[2]);                      \
    float _w3 = exp2_fast((c1)[3] + (c2)[3] + (c3)[3]);                      \
    num0 = fmaf((cz)[0], _w0, num0);                                         \
    num0 = fmaf((cz)[1], _w1, num0);                                         \
    num1 = fmaf((cz)[2], _w2, num1);                                         \
    num1 = fmaf((cz)[3], _w3, num1);                                         \
    den0 += _w0 + _w1;                                                       \
    den1 += _w2 + _w3;                                                       \
} while (0)

__global__ void __launch_bounds__(BLOCK, 3)
fuzzy_mma_kernel(const float* __restrict__ x,
                 const float* __restrict__ mu,
                 const float* __restrict__ sigma,
                 const float* __restrict__ rho,
                 float* __restrict__ out) {
    __shared__ __align__(16) float4 sBl[8 * 4 * 40];
    __shared__ __align__(8)  float2 sBz[8 * 2 * 48];
    __shared__ __align__(16) float2 sFB[64];

    const int tid = threadIdx.x;
    const int w = tid >> 5, lane = tid & 31;
    const int g = lane >> 2, tig = lane & 3;

    // ---- build fragment-packed B (once per CTA) ----
    for (int i = tid; i < 1024; i += BLOCK) {
        int gg = i & 7, tt = (i >> 3) & 3, ks = (i >> 5) & 3, j = i >> 7;
        int n = j * 8 + gg, k0 = ks * 8 + tt;
        float b0 = coefL(mu, sigma, n, k0);
        float b1 = coefL(mu, sigma, n, k0 + 4);
        float b0h = __uint_as_float(tf32_bits(b0));
        float b1h = __uint_as_float(tf32_bits(b1));
        sBl[FL(j, ks, tt, gg)] = make_float4(b0h, b1h, b0 - b0h, b1 - b1h);
    }
    for (int i = tid; i < 512; i += BLOCK) {
        int gg = i & 7, tt = (i >> 3) & 3, ks = (i >> 5) & 1, j = i >> 6;
        int n = j * 8 + gg, k0 = ks * 8 + tt;
        sBz[FZ(j, ks, tt, gg)] =
            make_float2(__uint_as_float(tf32_bits(rho[n * 17 + k0])),
                        __uint_as_float(tf32_bits(rho[n * 17 + k0 + 4])));
    }
    if (tid < 64) {
        float f = 0.0f;
        for (int a = 0; a < 16; a++) {
            float m = mu[tid * 16 + a], s = sigma[tid * 16 + a];
            f -= m * m * __fdividef(0.5f, s * s);
        }
        sFB[tid] = make_float2(f * LOG2E, rho[tid * 17 + 16]);
    }
    __syncthreads();

    // ---- persistent loop over 64-row tiles (1 m-tile per warp) ----
    for (int t = blockIdx.x; t < NTILES; t += GRID) {
        const int rowBase = t * 64 + w * 16;

        u32 ah[4][4], al[4][4];
#pragma unroll
        for (int rh = 0; rh < 2; rh++) {
            const float* xr = x + (size_t)(rowBase + rh * 8 + g) * 16 + tig;
#pragma unroll
            for (int e = 0; e < 4; e++) {
                float v = xr[4 * e];
                u32 vh = tf32_bits(v);
                u32 vl = tf32_bits(v - __uint_as_float(vh));
                float v2 = v * v;
                u32 v2h = tf32_bits(v2);
                u32 v2l = tf32_bits(v2 - __uint_as_float(v2h));
                int ks = e >> 1;
                int slot = (e & 1) * 2 + rh;
                ah[ks][slot] = vh;      al[ks][slot] = vl;
                ah[2 + ks][slot] = v2h; al[2 + ks][slot] = v2l;
            }
        }

        float num0 = 0.f, den0 = 0.f, num1 = 0.f, den1 = 0.f;

        // ---- ping-pong pipelined chunk loop ----
        float a1[4], a2[4], a3[4], azz[4];   // buffer A
        float b1[4], b2[4], b3[4], bzz[4];   // buffer B

        CHUNK_MMA(a1, a2, a3, azz, 0);
        for (int jj = 0; jj < 6; jj += 2) {
            CHUNK_MMA(b1, b2, b3, bzz, jj + 1);
            CHUNK_EPI(a1, a2, a3, azz);
            CHUNK_MMA(a1, a2, a3, azz, jj + 2);
            CHUNK_EPI(b1, b2, b3, bzz);
        }
        CHUNK_MMA(b1, b2, b3, bzz, 7);
        CHUNK_EPI(a1, a2, a3, azz);
        CHUNK_EPI(b1, b2, b3, bzz);

        // ---- reduce across 4 tig lanes; tig==0 writes rows g, g+8 ----
        num0 += __shfl_xor_sync(0xffffffffu, num0, 1);
        den0 += __shfl_xor_sync(0xffffffffu, den0, 1);
        num0 += __shfl_xor_sync(0xffffffffu, num0, 2);
        den0 += __shfl_xor_sync(0xffffffffu, den0, 2);
        num1 += __shfl_xor_sync(0xffffffffu, num1, 1);
        den1 += __shfl_xor_sync(0xffffffffu, den1, 1);
        num1 += __shfl_xor_sync(0xffffffffu, num1, 2);
        den1 += __shfl_xor_sync(0xffffffffu, den1, 2);
        if (tig == 0) {
            out[rowBase + g] = num0 / (den0 + 1e-13f);
            out[rowBase + 8 + g] = num1 / (den1 + 1e-13f);
        }
    }
}

extern "C" void kernel_launch(void* const* d_in, const int* in_sizes, int n_in,
                              void* d_out, int out_size) {
    const float* x = (const float*)d_in[0];      // [N, 16]
    const float* mu = (const float*)d_in[1];     // [64, 16]
    const float* sigma = (const float*)d_in[2];  // [64, 16]
    const float* rho = (const float*)d_in[3];    // [64, 17]
    float* out = (float*)d_out;                  // [N]

    fuzzy_mma_kernel<<<GRID, BLOCK>>>(x, mu, sigma, rho, out);
}